// round 1
// baseline (speedup 1.0000x reference)
#include <cuda_runtime.h>
#include <math.h>

#define NHIT 80000
#define KOBJ 512
#define TILE 256

// ---------------- scratch (device globals; no allocation allowed) ----------------
__device__ float4 g_hit[NHIT];                 // x, y, q, t_idx (as int bits)
__device__ float4 g_alpha[KOBJ];               // x_a, y_a, q_a, beta_a
__device__ unsigned long long g_amax[KOBJ];    // packed (beta_bits<<32 | ~idx)
__device__ int   g_cnt[KOBJ];
__device__ float g_num[KOBJ], g_den[KOBJ], g_att[KOBJ], g_rep[KOBJ];
__device__ float g_noise_sum, g_noise_cnt, g_cc_sum;

__device__ __forceinline__ float softclip_f(float x, float c) {
    x = x / c;
    if (x > 1.0f) x = logf(x + 1.0f);
    return x * c;
}
__device__ __forceinline__ float huber_f(float x, float d) {
    float ax = fabsf(x);
    return ax < d ? x * x : d * d + 2.0f * d * (ax - d);
}

// ---------------- kernel 1: init (runs every launch: graph-replay safe) ----------------
__global__ void k_init() {
    int k = blockIdx.x * blockDim.x + threadIdx.x;
    if (k < KOBJ) {
        g_amax[k] = 0ull;
        g_cnt[k] = 0;
        g_num[k] = 0.0f; g_den[k] = 0.0f;
        g_att[k] = 0.0f; g_rep[k] = 0.0f;
    }
    if (k == 0) { g_noise_sum = 0.0f; g_noise_cnt = 0.0f; g_cc_sum = 0.0f; }
}

// ---------------- kernel 2: per-hit pass ----------------
__global__ void k_hits(const float* __restrict__ pb,  const float* __restrict__ cc,
                       const float* __restrict__ pe,  const float* __restrict__ pp,
                       const float* __restrict__ pt,  const float* __restrict__ pid,
                       const int*   __restrict__ tix, const float* __restrict__ te,
                       const float* __restrict__ tp,  const float* __restrict__ tt,
                       const float* __restrict__ tpid) {
    int i = blockIdx.x * blockDim.x + threadIdx.x;
    float ns = 0.0f, ncnt = 0.0f, ccs = 0.0f;
    if (i < NHIT) {
        float beta = fminf(fmaxf(pb[i], 1e-6f), 1.0f - 1e-6f);
        float at = atanhf(beta);
        float q = at * at + 0.1f;
        float x = cc[2 * i], y = cc[2 * i + 1];
        int t = tix[i];
        g_hit[i] = make_float4(x, y, q, __int_as_float(t));
        ccs = x * x + y * y;
        if (t >= 0) {
            atomicAdd(&g_cnt[t], 1);
            // argmax beta, ties -> lowest index (matches jnp.argmax)
            unsigned long long key =
                (((unsigned long long)__float_as_uint(beta)) << 32) |
                (unsigned long long)(0xFFFFFFFFu - (unsigned)i);
            atomicMax(&g_amax[t], key);

            // payload losses
            float tei = te[i];
            float ed = fabsf(tei - pe[i]);
            float el = softclip_f(10.0f * expf(-0.1f * ed * ed) + 0.01f * ed, 10.0f);

            float dx = tp[2 * i] - pp[2 * i];
            float dy = tp[2 * i + 1] - pp[2 * i + 1];
            float pl = softclip_f(huber_f(sqrtf((dx * dx + dy * dy) * 0.01f + 0.01f), 10.0f), 3.0f);

            float tl = softclip_f(huber_f(tt[i] - pt[i], 2.0f), 6.0f);

            float s2 = 0.0f;
            #pragma unroll
            for (int j = 0; j < 6; j++) { float v = pid[6 * i + j]; s2 += v * v; }
            float cl = 1e-8f * (s2 * (1.0f / 6.0f));

            float payload = el + pl + tl + cl;
            float w = tei > 10.0f ? 1.0f : fmaxf((tei - 0.5f) * (1.0f / 9.5f), 0.0f);
            float pw = beta * w;
            atomicAdd(&g_num[t], payload * pw);
            atomicAdd(&g_den[t], pw);
        } else {
            ns = beta; ncnt = 1.0f;
        }
    }
    // warp reduce scalar accumulators; 1 atomic per warp per scalar
    #pragma unroll
    for (int o = 16; o > 0; o >>= 1) {
        ns   += __shfl_down_sync(0xFFFFFFFF, ns, o);
        ncnt += __shfl_down_sync(0xFFFFFFFF, ncnt, o);
        ccs  += __shfl_down_sync(0xFFFFFFFF, ccs, o);
    }
    if ((threadIdx.x & 31) == 0) {
        atomicAdd(&g_noise_sum, ns);
        atomicAdd(&g_noise_cnt, ncnt);
        atomicAdd(&g_cc_sum, ccs);
    }
}

// ---------------- kernel 3: gather condensation points ----------------
__global__ void k_alpha(const float* __restrict__ pb, const float* __restrict__ cc) {
    int k = threadIdx.x;
    if (k >= KOBJ) return;
    if (g_cnt[k] > 0) {
        unsigned idx = 0xFFFFFFFFu - (unsigned)(g_amax[k] & 0xFFFFFFFFull);
        float beta = fminf(fmaxf(pb[idx], 1e-6f), 1.0f - 1e-6f);
        float at = atanhf(beta);
        g_alpha[k] = make_float4(cc[2 * idx], cc[2 * idx + 1], at * at + 0.1f, beta);
    } else {
        // q_a = 0 kills attraction and repulsion for empty objects
        g_alpha[k] = make_float4(0.0f, 0.0f, 0.0f, 1.0f);
    }
}

// ---------------- kernel 4: N x K pair pass (the hot loop) ----------------
__global__ void __launch_bounds__(KOBJ) k_pairs() {
    __shared__ float4 sh[TILE];
    int k = threadIdx.x;
    float4 a = g_alpha[k];
    float att = 0.0f, rep = 0.0f;

    int base = blockIdx.x * TILE;
    int cnt = NHIT - base; if (cnt > TILE) cnt = TILE;

    for (int j = threadIdx.x; j < cnt; j += blockDim.x) sh[j] = g_hit[base + j];
    __syncthreads();

    #pragma unroll 4
    for (int j = 0; j < cnt; j++) {
        float4 h = sh[j];                    // broadcast LDS.128
        float dx = h.x - a.x;
        float dy = h.y - a.y;
        float d2 = fmaf(dx, dx, dy * dy);
        float s;
        asm("sqrt.approx.f32 %0, %1;" : "=f"(s) : "f"(d2 + 1e-6f));
        float r = fmaxf(1.0f - s, 0.0f) * h.z;
        bool member = (__float_as_int(h.w) == k);
        att += member ? d2 * h.z : 0.0f;
        rep += member ? 0.0f : r;
    }
    if (a.z > 0.0f) {
        atomicAdd(&g_att[k], att * a.z);
        atomicAdd(&g_rep[k], rep * a.z);
    }
}

// ---------------- kernel 5: finalize ----------------
__global__ void k_final(float* __restrict__ out) {
    __shared__ float s_obj[KOBJ];
    __shared__ float s_has[KOBJ];
    int k = threadIdx.x;
    int c = g_cnt[k];
    float obj = 0.0f, has = 0.0f;
    if (c > 0) {
        has = 1.0f;
        float fc = (float)c;
        obj = g_att[k] / (fc + 1e-9f)
            + g_rep[k] / ((float)NHIT - fc + 1e-9f)
            + g_num[k] / (g_den[k] + 1e-9f)
            + (1.0f - g_alpha[k].w);
    }
    s_obj[k] = obj; s_has[k] = has;
    __syncthreads();
    #pragma unroll
    for (int o = KOBJ / 2; o > 0; o >>= 1) {
        if (k < o) { s_obj[k] += s_obj[k + o]; s_has[k] += s_has[k + o]; }
        __syncthreads();
    }
    if (k == 0) {
        float n_obj = s_has[0] + 1e-9f;
        float total = s_obj[0] / n_obj
                    + g_noise_sum / (g_noise_cnt + 1e-9f)
                    + 0.001f * g_cc_sum * (1.0f / (float)(NHIT * 2));
        out[0] = total;
    }
}

// ---------------- launch ----------------
extern "C" void kernel_launch(void* const* d_in, const int* in_sizes, int n_in,
                              void* d_out, int out_size) {
    const float* pb  = (const float*)d_in[0];
    const float* cc  = (const float*)d_in[1];
    const float* pe  = (const float*)d_in[2];
    const float* pp  = (const float*)d_in[3];
    const float* pt  = (const float*)d_in[4];
    const float* pid = (const float*)d_in[5];
    const int*   tix = (const int*)  d_in[6];
    const float* te  = (const float*)d_in[7];
    const float* tp  = (const float*)d_in[8];
    const float* tt  = (const float*)d_in[9];
    const float* tpd = (const float*)d_in[10];

    k_init<<<1, KOBJ>>>();
    k_hits<<<(NHIT + 255) / 256, 256>>>(pb, cc, pe, pp, pt, pid, tix, te, tp, tt, tpd);
    k_alpha<<<1, KOBJ>>>(pb, cc);
    k_pairs<<<(NHIT + TILE - 1) / TILE, KOBJ>>>();
    k_final<<<1, KOBJ>>>((float*)d_out);
}

// round 2
// speedup vs baseline: 1.1531x; 1.1531x over previous
#include <cuda_runtime.h>
#include <math.h>

#define NHIT 80000
#define TILE 256
#define NPAD (313 * TILE)      // 80128, pad hits are inert (q=0, t=-1)
#define KOBJ 512
#define KHALF 256

// ---------------- scratch (device globals; zero at module load, reset by finalize) ----
__device__ float4 g_hit[NPAD];                 // x, y, q, t_idx (int bits)
__device__ unsigned long long g_amax[KOBJ];    // packed (beta_bits<<32 | ~idx)
__device__ int   g_cnt[KOBJ];
__device__ float g_num[KOBJ], g_den[KOBJ], g_att[KOBJ], g_rep[KOBJ];
__device__ float g_noise_sum, g_noise_cnt, g_cc_sum;
__device__ unsigned g_done;

__device__ __forceinline__ float softclip_f(float x, float c) {
    x = x / c;
    if (x > 1.0f) x = logf(x + 1.0f);
    return x * c;
}
__device__ __forceinline__ float huber_f(float x, float d) {
    float ax = fabsf(x);
    return ax < d ? x * x : d * d + 2.0f * d * (ax - d);
}

// ---------------- kernel 1: per-hit pass ----------------
__global__ void __launch_bounds__(256) k_hits(
        const float* __restrict__ pb,  const float* __restrict__ cc,
        const float* __restrict__ pe,  const float* __restrict__ pp,
        const float* __restrict__ pt,  const float* __restrict__ pid,
        const int*   __restrict__ tix, const float* __restrict__ te,
        const float* __restrict__ tp,  const float* __restrict__ tt) {
    int i = blockIdx.x * blockDim.x + threadIdx.x;
    float ns = 0.0f, ncnt = 0.0f, ccs = 0.0f;
    if (i < NHIT) {
        float beta = fminf(fmaxf(pb[i], 1e-6f), 1.0f - 1e-6f);
        float at = atanhf(beta);
        float q = at * at + 0.1f;
        float x = cc[2 * i], y = cc[2 * i + 1];
        int t = tix[i];
        g_hit[i] = make_float4(x, y, q, __int_as_float(t));
        ccs = x * x + y * y;
        if (t >= 0) {
            atomicAdd(&g_cnt[t], 1);
            // argmax beta, ties -> lowest index (matches jnp.argmax)
            unsigned long long key =
                (((unsigned long long)__float_as_uint(beta)) << 32) |
                (unsigned long long)(0xFFFFFFFFu - (unsigned)i);
            atomicMax(&g_amax[t], key);

            float tei = te[i];
            float ed = fabsf(tei - pe[i]);
            float el = softclip_f(10.0f * expf(-0.1f * ed * ed) + 0.01f * ed, 10.0f);

            float dx = tp[2 * i] - pp[2 * i];
            float dy = tp[2 * i + 1] - pp[2 * i + 1];
            float pl = softclip_f(huber_f(sqrtf((dx * dx + dy * dy) * 0.01f + 0.01f), 10.0f), 3.0f);

            float tl = softclip_f(huber_f(tt[i] - pt[i], 2.0f), 6.0f);

            float s2 = 0.0f;
            #pragma unroll
            for (int j = 0; j < 6; j++) { float v = pid[6 * i + j]; s2 += v * v; }
            float cl = 1e-8f * (s2 * (1.0f / 6.0f));

            float payload = el + pl + tl + cl;
            float w = tei > 10.0f ? 1.0f : fmaxf((tei - 0.5f) * (1.0f / 9.5f), 0.0f);
            float pw = beta * w;
            atomicAdd(&g_num[t], payload * pw);
            atomicAdd(&g_den[t], pw);
        } else {
            ns = beta; ncnt = 1.0f;
        }
    } else if (i < NPAD) {
        g_hit[i] = make_float4(0.0f, 0.0f, 0.0f, __int_as_float(-1));  // inert pad
    }
    #pragma unroll
    for (int o = 16; o > 0; o >>= 1) {
        ns   += __shfl_down_sync(0xFFFFFFFF, ns, o);
        ncnt += __shfl_down_sync(0xFFFFFFFF, ncnt, o);
        ccs  += __shfl_down_sync(0xFFFFFFFF, ccs, o);
    }
    if ((threadIdx.x & 31) == 0) {
        if (ns != 0.0f || ncnt != 0.0f) { atomicAdd(&g_noise_sum, ns); atomicAdd(&g_noise_cnt, ncnt); }
        atomicAdd(&g_cc_sum, ccs);
    }
}

// ---------------- kernel 2: N x K pair pass + fused alpha + fused finalize ----------------
__global__ void __launch_bounds__(KHALF) k_pairs(const float* __restrict__ pb,
                                                 const float* __restrict__ cc,
                                                 float* __restrict__ out) {
    __shared__ float4 sh[TILE];
    __shared__ float s_red[2 * KHALF];
    __shared__ unsigned s_last;

    const int t = threadIdx.x;
    const int k0 = t;            // object 0
    const int k1 = t + KHALF;    // object 1

    // --- per-block alpha recompute (L2-cached scattered loads, once per block) ---
    float ax0 = 0.f, ay0 = 0.f, aq0 = 0.f;
    float ax1 = 0.f, ay1 = 0.f, aq1 = 0.f;
    if (g_cnt[k0] > 0) {
        unsigned idx = 0xFFFFFFFFu - (unsigned)(g_amax[k0] & 0xFFFFFFFFull);
        float b = fminf(fmaxf(pb[idx], 1e-6f), 1.0f - 1e-6f);
        float a = atanhf(b);
        ax0 = cc[2 * idx]; ay0 = cc[2 * idx + 1]; aq0 = a * a + 0.1f;
    }
    if (g_cnt[k1] > 0) {
        unsigned idx = 0xFFFFFFFFu - (unsigned)(g_amax[k1] & 0xFFFFFFFFull);
        float b = fminf(fmaxf(pb[idx], 1e-6f), 1.0f - 1e-6f);
        float a = atanhf(b);
        ax1 = cc[2 * idx]; ay1 = cc[2 * idx + 1]; aq1 = a * a + 0.1f;
    }

    // --- hot loop: TILE hits vs 2 objects per thread ---
    float att0 = 0.f, rep0 = 0.f, att1 = 0.f, rep1 = 0.f;
    const int base = blockIdx.x * TILE;
    sh[t] = g_hit[base + t];
    __syncthreads();

    #pragma unroll 8
    for (int j = 0; j < TILE; j++) {
        float4 h = sh[j];                           // broadcast LDS.128
        int   ti = __float_as_int(h.w);
        float hq = h.z;

        float dx0 = h.x - ax0, dy0 = h.y - ay0;
        float d20 = fmaf(dx0, dx0, fmaf(dy0, dy0, 1e-6f));
        float s0; asm("sqrt.approx.f32 %0, %1;" : "=f"(s0) : "f"(d20));
        float r0 = __saturatef(1.0f - s0);
        if (ti == k0) att0 = fmaf(d20, hq, att0);
        else          rep0 = fmaf(r0,  hq, rep0);

        float dx1 = h.x - ax1, dy1 = h.y - ay1;
        float d21 = fmaf(dx1, dx1, fmaf(dy1, dy1, 1e-6f));
        float s1; asm("sqrt.approx.f32 %0, %1;" : "=f"(s1) : "f"(d21));
        float r1 = __saturatef(1.0f - s1);
        if (ti == k1) att1 = fmaf(d21, hq, att1);
        else          rep1 = fmaf(r1,  hq, rep1);
    }

    if (aq0 > 0.f) { atomicAdd(&g_att[k0], att0 * aq0); atomicAdd(&g_rep[k0], rep0 * aq0); }
    if (aq1 > 0.f) { atomicAdd(&g_att[k1], att1 * aq1); atomicAdd(&g_rep[k1], rep1 * aq1); }

    // --- last block finalizes + resets scratch for next graph replay ---
    __threadfence();
    if (t == 0) s_last = atomicAdd(&g_done, 1u);
    __syncthreads();
    if (s_last != gridDim.x - 1) return;

    float obj = 0.f, has = 0.f;
    #pragma unroll
    for (int kk = 0; kk < 2; kk++) {
        int k = t + kk * KHALF;
        int c = g_cnt[k];
        if (c > 0) {
            has += 1.0f;
            unsigned idx = 0xFFFFFFFFu - (unsigned)(g_amax[k] & 0xFFFFFFFFull);
            float ba = fminf(fmaxf(pb[idx], 1e-6f), 1.0f - 1e-6f);
            float fc = (float)c;
            obj += g_att[k] / (fc + 1e-9f)
                 + g_rep[k] / ((float)NHIT - fc + 1e-9f)
                 + g_num[k] / (g_den[k] + 1e-9f)
                 + (1.0f - ba);
        }
        // reset this object's scratch (disjoint per thread)
        g_amax[k] = 0ull; g_cnt[k] = 0;
        g_num[k] = 0.f; g_den[k] = 0.f; g_att[k] = 0.f; g_rep[k] = 0.f;
    }
    s_red[t] = obj; s_red[t + KHALF] = has;
    __syncthreads();
    #pragma unroll
    for (int o = KHALF / 2; o > 0; o >>= 1) {
        if (t < o) { s_red[t] += s_red[t + o]; s_red[t + KHALF] += s_red[t + KHALF + o]; }
        __syncthreads();
    }
    if (t == 0) {
        float n_obj = s_red[KHALF] + 1e-9f;
        float total = s_red[0] / n_obj
                    + g_noise_sum / (g_noise_cnt + 1e-9f)
                    + 0.001f * g_cc_sum * (1.0f / (float)(NHIT * 2));
        out[0] = total;
        // reset scalars for next replay
        g_noise_sum = 0.f; g_noise_cnt = 0.f; g_cc_sum = 0.f; g_done = 0u;
    }
}

// ---------------- launch ----------------
extern "C" void kernel_launch(void* const* d_in, const int* in_sizes, int n_in,
                              void* d_out, int out_size) {
    const float* pb  = (const float*)d_in[0];
    const float* cc  = (const float*)d_in[1];
    const float* pe  = (const float*)d_in[2];
    const float* pp  = (const float*)d_in[3];
    const float* pt  = (const float*)d_in[4];
    const float* pid = (const float*)d_in[5];
    const int*   tix = (const int*)  d_in[6];
    const float* te  = (const float*)d_in[7];
    const float* tp  = (const float*)d_in[8];
    const float* tt  = (const float*)d_in[9];

    k_hits<<<NPAD / 256, 256>>>(pb, cc, pe, pp, pt, pid, tix, te, tp, tt);
    k_pairs<<<NPAD / TILE, KHALF>>>(pb, cc, (float*)d_out);
}

// round 3
// speedup vs baseline: 1.2482x; 1.0825x over previous
#include <cuda_runtime.h>
#include <math.h>

#define NHIT 80000
#define TILE 128
#define NBLK 626               // 626 * 128 = 80128
#define NPAD (NBLK * TILE)
#define KOBJ 512
#define KHALF 256

// ---------------- scratch (device globals; zero at load, reset by finalize) ----------
__device__ float4 g_hit[NPAD];                 // x, y, q, t_idx (int bits)
__device__ float4 g_alpha[KOBJ];               // x_a, y_a, q_a, beta_a
__device__ unsigned long long g_amax[KOBJ];    // packed (beta_bits<<32 | ~idx)
__device__ int   g_cnt[KOBJ];
__device__ float g_num[KOBJ], g_den[KOBJ], g_att[KOBJ], g_rep[KOBJ];
__device__ float g_noise_sum, g_noise_cnt, g_cc_sum;
__device__ unsigned g_done;

__device__ __forceinline__ float clampb(float b) {
    return fminf(fmaxf(b, 1e-6f), 1.0f - 1e-6f);
}
__device__ __forceinline__ float softclip_f(float x, float c) {
    x = x * (1.0f / c);
    if (x > 1.0f) x = __logf(x + 1.0f);
    return x * c;
}
__device__ __forceinline__ float huber_f(float x, float d) {
    float ax = fabsf(x);
    return ax < d ? x * x : d * d + 2.0f * d * (ax - d);
}

// ---------------- kernel 1: per-hit pass ----------------
__global__ void __launch_bounds__(256) k_hits(
        const float* __restrict__ pb,  const float* __restrict__ cc,
        const float* __restrict__ pe,  const float* __restrict__ pp,
        const float* __restrict__ pt,  const float* __restrict__ pid,
        const int*   __restrict__ tix, const float* __restrict__ te,
        const float* __restrict__ tp,  const float* __restrict__ tt) {
    int i = blockIdx.x * blockDim.x + threadIdx.x;
    float ns = 0.0f, ncnt = 0.0f, ccs = 0.0f;
    if (i < NHIT) {
        float beta = clampb(pb[i]);
        // atanh(b)^2 = 0.25 * ln^2((1+b)/(1-b))
        float lg = __logf(__fdividef(1.0f + beta, 1.0f - beta));
        float q = fmaf(0.25f * lg, lg, 0.1f);
        float2 ccv = ((const float2*)cc)[i];
        int t = tix[i];
        g_hit[i] = make_float4(ccv.x, ccv.y, q, __int_as_float(t));
        ccs = ccv.x * ccv.x + ccv.y * ccv.y;
        if (t >= 0) {
            atomicAdd(&g_cnt[t], 1);
            // argmax beta, ties -> lowest index (matches jnp.argmax)
            unsigned long long key =
                (((unsigned long long)__float_as_uint(beta)) << 32) |
                (unsigned long long)(0xFFFFFFFFu - (unsigned)i);
            atomicMax(&g_amax[t], key);

            float tei = te[i];
            float ed = fabsf(tei - pe[i]);
            float el = softclip_f(fmaf(10.0f, __expf(-0.1f * ed * ed), 0.01f * ed), 10.0f);

            float2 tpv = ((const float2*)tp)[i];
            float2 ppv = ((const float2*)pp)[i];
            float dx = tpv.x - ppv.x, dy = tpv.y - ppv.y;
            float pl = softclip_f(huber_f(sqrtf(fmaf(dx, dx, dy * dy) * 0.01f + 0.01f), 10.0f), 3.0f);

            float tl = softclip_f(huber_f(tt[i] - pt[i], 2.0f), 6.0f);

            float s2 = 0.0f;
            #pragma unroll
            for (int j = 0; j < 6; j++) { float v = pid[6 * i + j]; s2 += v * v; }
            float cl = 1e-8f * (s2 * (1.0f / 6.0f));

            float payload = el + pl + tl + cl;
            float w = tei > 10.0f ? 1.0f : fmaxf((tei - 0.5f) * (1.0f / 9.5f), 0.0f);
            float pw = beta * w;
            atomicAdd(&g_num[t], payload * pw);
            atomicAdd(&g_den[t], pw);
        } else {
            ns = beta; ncnt = 1.0f;
        }
    } else if (i < NPAD) {
        g_hit[i] = make_float4(0.0f, 0.0f, 0.0f, __int_as_float(-1));  // inert pad
    }
    #pragma unroll
    for (int o = 16; o > 0; o >>= 1) {
        ns   += __shfl_down_sync(0xFFFFFFFF, ns, o);
        ncnt += __shfl_down_sync(0xFFFFFFFF, ncnt, o);
        ccs  += __shfl_down_sync(0xFFFFFFFF, ccs, o);
    }
    if ((threadIdx.x & 31) == 0) {
        if (ns != 0.0f || ncnt != 0.0f) { atomicAdd(&g_noise_sum, ns); atomicAdd(&g_noise_cnt, ncnt); }
        atomicAdd(&g_cc_sum, ccs);
    }
}

// ---------------- kernel 2: condensation points ----------------
__global__ void __launch_bounds__(KOBJ) k_alpha(const float* __restrict__ pb,
                                                const float* __restrict__ cc) {
    int k = threadIdx.x;
    if (g_cnt[k] > 0) {
        unsigned idx = 0xFFFFFFFFu - (unsigned)(g_amax[k] & 0xFFFFFFFFull);
        float b = clampb(pb[idx]);
        float lg = __logf(__fdividef(1.0f + b, 1.0f - b));
        float2 ccv = ((const float2*)cc)[idx];
        g_alpha[k] = make_float4(ccv.x, ccv.y, fmaf(0.25f * lg, lg, 0.1f), b);
    } else {
        g_alpha[k] = make_float4(0.0f, 0.0f, 0.0f, 1.0f);
    }
}

// ---------------- kernel 3: N x K pair pass + fused finalize ----------------
__global__ void __launch_bounds__(KHALF) k_pairs(float* __restrict__ out) {
    __shared__ float4 sh[TILE];
    __shared__ float s_red[2 * KHALF];
    __shared__ unsigned s_last;

    const int t = threadIdx.x;
    const int k0 = t;
    const int k1 = t + KHALF;

    float4 a0 = g_alpha[k0];
    float4 a1 = g_alpha[k1];

    float att0 = 0.f, rep0 = 0.f, att1 = 0.f, rep1 = 0.f;
    const int base = blockIdx.x * TILE;
    if (t < TILE) sh[t] = g_hit[base + t];
    __syncthreads();

    #pragma unroll 16
    for (int j = 0; j < TILE; j++) {
        float4 h = sh[j];                           // broadcast LDS.128
        int ti = __float_as_int(h.w);

        float dx0 = h.x - a0.x, dy0 = h.y - a0.y;
        float d20 = fmaf(dx0, dx0, fmaf(dy0, dy0, 1e-6f));
        asm("{ .reg .pred p;\n\t"
            " .reg .f32 s, r;\n\t"
            " sqrt.approx.f32 s, %4;\n\t"
            " sub.rn.sat.f32 r, 0f3F800000, s;\n\t"
            " setp.eq.s32 p, %2, %3;\n\t"
            " @p fma.rn.f32 %0, %4, %5, %0;\n\t"
            "@!p fma.rn.f32 %1, r, %5, %1;\n\t}"
            : "+f"(att0), "+f"(rep0)
            : "r"(ti), "r"(k0), "f"(d20), "f"(h.z));

        float dx1 = h.x - a1.x, dy1 = h.y - a1.y;
        float d21 = fmaf(dx1, dx1, fmaf(dy1, dy1, 1e-6f));
        asm("{ .reg .pred p;\n\t"
            " .reg .f32 s, r;\n\t"
            " sqrt.approx.f32 s, %4;\n\t"
            " sub.rn.sat.f32 r, 0f3F800000, s;\n\t"
            " setp.eq.s32 p, %2, %3;\n\t"
            " @p fma.rn.f32 %0, %4, %5, %0;\n\t"
            "@!p fma.rn.f32 %1, r, %5, %1;\n\t}"
            : "+f"(att1), "+f"(rep1)
            : "r"(ti), "r"(k1), "f"(d21), "f"(h.z));
    }

    if (a0.z > 0.f) { atomicAdd(&g_att[k0], att0 * a0.z); atomicAdd(&g_rep[k0], rep0 * a0.z); }
    if (a1.z > 0.f) { atomicAdd(&g_att[k1], att1 * a1.z); atomicAdd(&g_rep[k1], rep1 * a1.z); }

    // --- last block finalizes + resets scratch for next graph replay ---
    __threadfence();
    if (t == 0) s_last = atomicAdd(&g_done, 1u);
    __syncthreads();
    if (s_last != gridDim.x - 1) return;

    float obj = 0.f, has = 0.f;
    #pragma unroll
    for (int kk = 0; kk < 2; kk++) {
        int k = t + kk * KHALF;
        int c = g_cnt[k];
        if (c > 0) {
            has += 1.0f;
            float fc = (float)c;
            obj += g_att[k] / (fc + 1e-9f)
                 + g_rep[k] / ((float)NHIT - fc + 1e-9f)
                 + g_num[k] / (g_den[k] + 1e-9f)
                 + (1.0f - g_alpha[k].w);
        }
        g_amax[k] = 0ull; g_cnt[k] = 0;
        g_num[k] = 0.f; g_den[k] = 0.f; g_att[k] = 0.f; g_rep[k] = 0.f;
    }
    s_red[t] = obj; s_red[t + KHALF] = has;
    __syncthreads();
    #pragma unroll
    for (int o = KHALF / 2; o > 0; o >>= 1) {
        if (t < o) { s_red[t] += s_red[t + o]; s_red[t + KHALF] += s_red[t + KHALF + o]; }
        __syncthreads();
    }
    if (t == 0) {
        float n_obj = s_red[KHALF] + 1e-9f;
        float total = s_red[0] / n_obj
                    + g_noise_sum / (g_noise_cnt + 1e-9f)
                    + 0.001f * g_cc_sum * (1.0f / (float)(NHIT * 2));
        out[0] = total;
        g_noise_sum = 0.f; g_noise_cnt = 0.f; g_cc_sum = 0.f; g_done = 0u;
    }
}

// ---------------- launch ----------------
extern "C" void kernel_launch(void* const* d_in, const int* in_sizes, int n_in,
                              void* d_out, int out_size) {
    const float* pb  = (const float*)d_in[0];
    const float* cc  = (const float*)d_in[1];
    const float* pe  = (const float*)d_in[2];
    const float* pp  = (const float*)d_in[3];
    const float* pt  = (const float*)d_in[4];
    const float* pid = (const float*)d_in[5];
    const int*   tix = (const int*)  d_in[6];
    const float* te  = (const float*)d_in[7];
    const float* tp  = (const float*)d_in[8];
    const float* tt  = (const float*)d_in[9];

    k_hits<<<NPAD / 256, 256>>>(pb, cc, pe, pp, pt, pid, tix, te, tp, tt);
    k_alpha<<<1, KOBJ>>>(pb, cc);
    k_pairs<<<NBLK, KHALF>>>((float*)d_out);
}

// round 4
// speedup vs baseline: 1.4152x; 1.1338x over previous
#include <cuda_runtime.h>
#include <math.h>

#define NHIT 80000
#define TILE 128
#define NBLK 626               // 626 * 128 = 80128
#define NPAD (NBLK * TILE)
#define KOBJ 512
#define KHALF 256
#define HBLK 313               // k_hits blocks (256 thr)

// ---------------- scratch (device globals; zero at load, reset after use) ----------
__device__ float4 g_hit[NPAD];                 // x, y, q, t_idx (int bits)
__device__ float4 g_alpha[KOBJ];               // x_a, y_a, q_a, beta_a
__device__ unsigned long long g_amax[KOBJ];    // packed (beta_bits<<32 | ~idx)
__device__ int   g_cnt[KOBJ];
__device__ float g_num[KOBJ], g_den[KOBJ], g_att[KOBJ], g_rep[KOBJ];
__device__ float g_noise_sum, g_noise_cnt, g_cc_sum;
__device__ unsigned g_done_h, g_done_p;

__device__ __forceinline__ float clampb(float b) {
    return fminf(fmaxf(b, 1e-6f), 1.0f - 1e-6f);
}
__device__ __forceinline__ float softclip_f(float x, float c) {
    x = x * (1.0f / c);
    if (x > 1.0f) x = __logf(x + 1.0f);
    return x * c;
}
__device__ __forceinline__ float huber_f(float x, float d) {
    float ax = fabsf(x);
    return ax < d ? x * x : d * d + 2.0f * d * (ax - d);
}

// ---------------- kernel 1: per-hit pass + fused alpha gather ----------------
__global__ void __launch_bounds__(256) k_hits(
        const float* __restrict__ pb,  const float* __restrict__ cc,
        const float* __restrict__ pe,  const float* __restrict__ pp,
        const float* __restrict__ pt,  const float* __restrict__ pid,
        const int*   __restrict__ tix, const float* __restrict__ te,
        const float* __restrict__ tp,  const float* __restrict__ tt) {
    __shared__ unsigned s_last;
    int i = blockIdx.x * blockDim.x + threadIdx.x;
    float ns = 0.0f, ncnt = 0.0f, ccs = 0.0f;
    if (i < NHIT) {   // warp-uniform (80000 % 32 == 0)
        // ---- hoist ALL loads: ~9 independent LDGs in flight ----
        float  braw = pb[i];
        int    t    = tix[i];
        float2 ccv  = ((const float2*)cc)[i];
        float  pev  = pe[i];
        float2 ppv  = ((const float2*)pp)[i];
        float  ptv  = pt[i];
        float  tev  = te[i];
        float2 tpv  = ((const float2*)tp)[i];
        float  ttv  = tt[i];
        float2 pid0 = ((const float2*)pid)[3 * i];
        float2 pid1 = ((const float2*)pid)[3 * i + 1];
        float2 pid2 = ((const float2*)pid)[3 * i + 2];

        float beta = clampb(braw);
        // atanh(b)^2 = 0.25 * ln^2((1+b)/(1-b))
        float lg = __logf(__fdividef(1.0f + beta, 1.0f - beta));
        float q = fmaf(0.25f * lg, lg, 0.1f);
        g_hit[i] = make_float4(ccv.x, ccv.y, q, __int_as_float(t));
        ccs = ccv.x * ccv.x + ccv.y * ccv.y;

        // ---- payload (computed unconditionally; ~0.2% waste on noise) ----
        float ed = fabsf(tev - pev);
        float el = softclip_f(fmaf(10.0f, __expf(-0.1f * ed * ed), 0.01f * ed), 10.0f);
        float dx = tpv.x - ppv.x, dy = tpv.y - ppv.y;
        float pl = softclip_f(huber_f(sqrtf(fmaf(dx, dx, dy * dy) * 0.01f + 0.01f), 10.0f), 3.0f);
        float tl = softclip_f(huber_f(ttv - ptv, 2.0f), 6.0f);
        float s2 = pid0.x * pid0.x + pid0.y * pid0.y + pid1.x * pid1.x
                 + pid1.y * pid1.y + pid2.x * pid2.x + pid2.y * pid2.y;
        float cl = 1e-8f * (s2 * (1.0f / 6.0f));
        float payload = el + pl + tl + cl;
        float w = tev > 10.0f ? 1.0f : fmaxf((tev - 0.5f) * (1.0f / 9.5f), 0.0f);
        float pw = beta * w;

        if (t >= 0) {
            atomicAdd(&g_cnt[t], 1);
            // argmax beta, ties -> lowest index (matches jnp.argmax)
            unsigned long long key =
                (((unsigned long long)__float_as_uint(beta)) << 32) |
                (unsigned long long)(0xFFFFFFFFu - (unsigned)i);
            atomicMax(&g_amax[t], key);
            atomicAdd(&g_num[t], payload * pw);
            atomicAdd(&g_den[t], pw);
        } else {
            ns = beta; ncnt = 1.0f;
        }
    } else {
        g_hit[i] = make_float4(0.0f, 0.0f, 0.0f, __int_as_float(-1));  // inert pad
    }
    #pragma unroll
    for (int o = 16; o > 0; o >>= 1) {
        ns   += __shfl_down_sync(0xFFFFFFFF, ns, o);
        ncnt += __shfl_down_sync(0xFFFFFFFF, ncnt, o);
        ccs  += __shfl_down_sync(0xFFFFFFFF, ccs, o);
    }
    if ((threadIdx.x & 31) == 0) {
        if (ns != 0.0f || ncnt != 0.0f) { atomicAdd(&g_noise_sum, ns); atomicAdd(&g_noise_cnt, ncnt); }
        atomicAdd(&g_cc_sum, ccs);
    }

    // ---- last block gathers condensation points (replaces k_alpha launch) ----
    __threadfence();
    if (threadIdx.x == 0) s_last = atomicAdd(&g_done_h, 1u);
    __syncthreads();
    if (s_last != gridDim.x - 1) return;

    #pragma unroll
    for (int kk = 0; kk < 2; kk++) {
        int k = threadIdx.x + kk * KHALF;
        if (g_cnt[k] > 0) {
            unsigned idx = 0xFFFFFFFFu - (unsigned)(g_amax[k] & 0xFFFFFFFFull);
            float b = clampb(pb[idx]);
            float lg = __logf(__fdividef(1.0f + b, 1.0f - b));
            float2 ccv = ((const float2*)cc)[idx];
            g_alpha[k] = make_float4(ccv.x, ccv.y, fmaf(0.25f * lg, lg, 0.1f), b);
        } else {
            g_alpha[k] = make_float4(0.0f, 0.0f, 0.0f, 1.0f);
        }
    }
    if (threadIdx.x == 0) g_done_h = 0u;   // reset for next graph replay
}

// ---------------- kernel 2: N x K pair pass + fused finalize ----------------
__global__ void __launch_bounds__(KHALF) k_pairs(float* __restrict__ out) {
    __shared__ float4 sh[TILE];
    __shared__ float s_red[2 * KHALF];
    __shared__ unsigned s_last;

    const int t = threadIdx.x;
    const int k0 = t;
    const int k1 = t + KHALF;

    float4 a0 = g_alpha[k0];
    float4 a1 = g_alpha[k1];

    float att0 = 0.f, rep0 = 0.f, att1 = 0.f, rep1 = 0.f;
    const int base = blockIdx.x * TILE;
    if (t < TILE) sh[t] = g_hit[base + t];
    __syncthreads();

    #pragma unroll 16
    for (int j = 0; j < TILE; j++) {
        float4 h = sh[j];                           // broadcast LDS.128
        int ti = __float_as_int(h.w);

        float dx0 = h.x - a0.x, dy0 = h.y - a0.y;
        float d20 = fmaf(dx0, dx0, fmaf(dy0, dy0, 1e-6f));
        asm("{ .reg .pred p;\n\t"
            " .reg .f32 s, r;\n\t"
            " sqrt.approx.f32 s, %4;\n\t"
            " sub.rn.sat.f32 r, 0f3F800000, s;\n\t"
            " setp.eq.s32 p, %2, %3;\n\t"
            " @p fma.rn.f32 %0, %4, %5, %0;\n\t"
            "@!p fma.rn.f32 %1, r, %5, %1;\n\t}"
            : "+f"(att0), "+f"(rep0)
            : "r"(ti), "r"(k0), "f"(d20), "f"(h.z));

        float dx1 = h.x - a1.x, dy1 = h.y - a1.y;
        float d21 = fmaf(dx1, dx1, fmaf(dy1, dy1, 1e-6f));
        asm("{ .reg .pred p;\n\t"
            " .reg .f32 s, r;\n\t"
            " sqrt.approx.f32 s, %4;\n\t"
            " sub.rn.sat.f32 r, 0f3F800000, s;\n\t"
            " setp.eq.s32 p, %2, %3;\n\t"
            " @p fma.rn.f32 %0, %4, %5, %0;\n\t"
            "@!p fma.rn.f32 %1, r, %5, %1;\n\t}"
            : "+f"(att1), "+f"(rep1)
            : "r"(ti), "r"(k1), "f"(d21), "f"(h.z));
    }

    if (a0.z > 0.f) { atomicAdd(&g_att[k0], att0 * a0.z); atomicAdd(&g_rep[k0], rep0 * a0.z); }
    if (a1.z > 0.f) { atomicAdd(&g_att[k1], att1 * a1.z); atomicAdd(&g_rep[k1], rep1 * a1.z); }

    // --- last block finalizes + resets scratch for next graph replay ---
    __threadfence();
    if (t == 0) s_last = atomicAdd(&g_done_p, 1u);
    __syncthreads();
    if (s_last != gridDim.x - 1) return;

    float obj = 0.f, has = 0.f;
    #pragma unroll
    for (int kk = 0; kk < 2; kk++) {
        int k = t + kk * KHALF;
        int c = g_cnt[k];
        if (c > 0) {
            has += 1.0f;
            float fc = (float)c;
            obj += g_att[k] / (fc + 1e-9f)
                 + g_rep[k] / ((float)NHIT - fc + 1e-9f)
                 + g_num[k] / (g_den[k] + 1e-9f)
                 + (1.0f - g_alpha[k].w);
        }
        g_amax[k] = 0ull; g_cnt[k] = 0;
        g_num[k] = 0.f; g_den[k] = 0.f; g_att[k] = 0.f; g_rep[k] = 0.f;
    }
    s_red[t] = obj; s_red[t + KHALF] = has;
    __syncthreads();
    #pragma unroll
    for (int o = KHALF / 2; o > 0; o >>= 1) {
        if (t < o) { s_red[t] += s_red[t + o]; s_red[t + KHALF] += s_red[t + KHALF + o]; }
        __syncthreads();
    }
    if (t == 0) {
        float n_obj = s_red[KHALF] + 1e-9f;
        float total = s_red[0] / n_obj
                    + g_noise_sum / (g_noise_cnt + 1e-9f)
                    + 0.001f * g_cc_sum * (1.0f / (float)(NHIT * 2));
        out[0] = total;
        g_noise_sum = 0.f; g_noise_cnt = 0.f; g_cc_sum = 0.f; g_done_p = 0u;
    }
}

// ---------------- launch ----------------
extern "C" void kernel_launch(void* const* d_in, const int* in_sizes, int n_in,
                              void* d_out, int out_size) {
    const float* pb  = (const float*)d_in[0];
    const float* cc  = (const float*)d_in[1];
    const float* pe  = (const float*)d_in[2];
    const float* pp  = (const float*)d_in[3];
    const float* pt  = (const float*)d_in[4];
    const float* pid = (const float*)d_in[5];
    const int*   tix = (const int*)  d_in[6];
    const float* te  = (const float*)d_in[7];
    const float* tp  = (const float*)d_in[8];
    const float* tt  = (const float*)d_in[9];

    k_hits<<<HBLK, 256>>>(pb, cc, pe, pp, pt, pid, tix, te, tp, tt);
    k_pairs<<<NBLK, KHALF>>>((float*)d_out);
}